// round 16
// baseline (speedup 1.0000x reference)
#include <cuda_runtime.h>
#include <math.h>

// Problem constants (fixed by the reference: B=16, N=4096, Z=128)
#define BB 16
#define NN 4096
#define ZZ 128

#define THREADS 512
#define Q 8                     // preds per thread: 512*8 = 4096 = ALL preds of the batch
#define NCTA 296                // 2 CTAs/SM on 148 SMs: all co-resident -> grid barrier safe
#define GTSMAX 232              // max gt-chunk (<=228 actual, padded)
#define NWARPS (THREADS / 32)   // 16
#define NKEYS (BB * NN)         // 65536

// Encoded row-min keys: zero-init == identity for atomicMax == +inf in min-space.
__device__ unsigned g_rmkey[NKEYS];     // 256KB, L2-resident
__device__ float    g_part2[NCTA];
__device__ int      g_c1 = 0;
__device__ int      g_c2 = 0;

// Full monotone-DECREASING float->uint map (min(v) <=> max(key)), identity 0.
__device__ __forceinline__ unsigned enc_min(float v) {
    unsigned b = __float_as_uint(v);
    return (b & 0x80000000u) ? b : (~b & 0x7FFFFFFFu);
}
__device__ __forceinline__ float dec_min(unsigned m) {
    return __uint_as_float((m & 0x80000000u) ? m : (~m & 0x7FFFFFFFu));
}

// CHEAP encoding for v >= 0 (true squared distances): key = ~bits, single LOP.
__device__ __forceinline__ unsigned enc_nn(float v) {
    return ~__float_as_uint(v);
}
__device__ __forceinline__ float dec_nn(unsigned m) {
    return __uint_as_float(~m);
}

// Warp-wide max reduction in ONE instruction.
__device__ __forceinline__ unsigned warp_redux_max(unsigned v) {
    unsigned r;
    asm("redux.sync.max.u32 %0, %1, 0xffffffff;" : "=r"(r) : "r"(v));
    return r;
}

// FFMA with immediate 1.0 multiplier: rt_SMSP=1
__device__ __forceinline__ float fma_i1(float a, float c) {
    float d;
    asm("fma.rn.f32 %0, %1, 0f3F800000, %2;" : "=f"(d) : "f"(a), "f"(c));
    return d;
}

// Persistent fused kernel (converged structure, R15 + ILP polish).
// Phase 1: CTA = (batch, balanced gt-chunk), ALL 4096 preds in registers.
//   t' = (||g||^2 + ||p||^2) - 2 g.p = P[j,q]  (imm-FFMA seed + 3 FFMA)
//   row-min: mn[q] = min(mn[q], t')  -> global atomicMax key merge (exact)
//   col-min: ca    = min(ca,   t')  -> redux.sync key, stored one pair late
// Grid barrier (all 296 CTAs co-resident), distributed fold + KL, ticket-last
// CTA writes out[0]. One launch total.
__global__ __launch_bounds__(THREADS, 2)
void chamfer_fused(const float* __restrict__ preds,
                   const float* __restrict__ gts,
                   const float* __restrict__ mu,
                   const float* __restrict__ logvar,
                   float* __restrict__ out)
{
    __shared__ float4   sg[GTSMAX];             // (-2gx, -2gy, -2gz, ||g||^2)
    __shared__ unsigned scol[NWARPS * GTSMAX];  // per-warp col-min KEYS (~bits)
    __shared__ float    red[THREADS];
    __shared__ int      slast;

    // Balanced (batch, chunk) assignment: batches 0-7 -> 19 CTAs, 8-15 -> 18.
    const int cta = blockIdx.x;
    int batch, idx, C;
    if (cta < 152) { batch = cta / 19;            idx = cta % 19;        C = 19; }
    else           { batch = 8 + (cta - 152) / 18; idx = (cta - 152) % 18; C = 18; }
    const int gA  = 2 * ((idx * (NN / 2)) / C);              // even start
    const int cnt = 2 * (((idx + 1) * (NN / 2)) / C) - gA;   // even, <= 228

    const float* __restrict__ pb = preds + batch * 3 * NN;

    const int tid   = threadIdx.x;
    const int wid   = tid >> 5;
    const bool lane0 = (tid & 31) == 0;

    // Stage this CTA's gt chunk (coalesced per-channel loads, pre-scale by -2)
    {
        const float* __restrict__ gb = gts + batch * 3 * NN;
        for (int i = tid; i < cnt; i += THREADS) {
            const int n = gA + i;
            const float x0 = gb[n];
            const float x1 = gb[NN + n];
            const float x2 = gb[2 * NN + n];
            sg[i] = make_float4(-2.0f * x0, -2.0f * x1, -2.0f * x2,
                                x0 * x0 + x1 * x1 + x2 * x2);
        }
    }

    // This thread's 8 preds in registers
    float px[Q], py[Q], pz[Q], rp[Q], mn[Q];
#pragma unroll
    for (int q = 0; q < Q; q++) {
        const int m = tid + q * THREADS;
        px[q] = pb[m];
        py[q] = pb[NN + m];
        pz[q] = pb[2 * NN + m];
        rp[q] = px[q] * px[q] + py[q] * py[q] + pz[q] * pz[q];
        mn[q] = 3.4e38f;
    }
    __syncthreads();

    // Main sweep, 2 gts per trip, unrolled x2 for cross-pair ILP. rp folded
    // into the FFMA seed so t' = P[j,q] feeds BOTH mins directly. Col keys
    // stored one pair late as a single 64-bit STS (software pipeline).
    {
        unsigned* __restrict__ sc = scol + wid * GTSMAX;
        unsigned kp0 = 0u, kp1 = 0u;
#pragma unroll 2
        for (int j = 0; j < cnt; j += 2) {
            if (lane0 && j > 0)            // previous pair's keys, one STS.64
                *(uint2*)(sc + (j - 2)) = make_uint2(kp0, kp1);
            const float4 g0 = sg[j];
            const float4 g1 = sg[j + 1];
            float ca0 = 3.4e38f, ca1 = 3.4e38f;
#pragma unroll
            for (int q = 0; q < Q; q += 2) {
                const float s0a = fma_i1(g0.w, rp[q]);     // seeds: off critical path
                const float s0b = fma_i1(g0.w, rp[q+1]);
                const float s1a = fma_i1(g1.w, rp[q]);
                const float s1b = fma_i1(g1.w, rp[q+1]);
                float t00 = fmaf(g0.x, px[q],   fmaf(g0.y, py[q],   fmaf(g0.z, pz[q],   s0a)));
                float t01 = fmaf(g0.x, px[q+1], fmaf(g0.y, py[q+1], fmaf(g0.z, pz[q+1], s0b)));
                float t10 = fmaf(g1.x, px[q],   fmaf(g1.y, py[q],   fmaf(g1.z, pz[q],   s1a)));
                float t11 = fmaf(g1.x, px[q+1], fmaf(g1.y, py[q+1], fmaf(g1.z, pz[q+1], s1b)));
                mn[q]   = fminf(mn[q],   fminf(t00, t10));
                mn[q+1] = fminf(mn[q+1], fminf(t01, t11));
                ca0 = fminf(ca0, fminf(t00, t01));
                ca1 = fminf(ca1, fminf(t10, t11));
            }
            // ca0/ca1 are true squared distances (>= 0): single-NOT encoding.
            kp0 = warp_redux_max(enc_nn(ca0));
            kp1 = warp_redux_max(enc_nn(ca1));
        }
        if (lane0)                         // drain the pipeline
            *(uint2*)(sc + (cnt - 2)) = make_uint2(kp0, kp1);
    }

    // Merge partial row-mins across gt-chunks: encoded atomicMax (full safe
    // encoding; exact, order-independent). mn already includes rp (it is P).
#pragma unroll
    for (int q = 0; q < Q; q++) {
        const int p = tid + q * THREADS;
        atomicMax(&g_rmkey[batch * NN + p], enc_min(mn[q]));
    }

    __syncthreads();

    // Cross-warp col-min reduce (integer max on ~bits keys) + sum over gts
    float s = 0.0f;
    for (int i = tid; i < cnt; i += THREADS) {
        unsigned c = scol[i];
#pragma unroll
        for (int w = 1; w < NWARPS; w++)
            c = max(c, scol[w * GTSMAX + i]);
        s += dec_nn(c);
    }
    red[tid] = s;
    __syncthreads();
    for (int off = THREADS / 2; off > 0; off >>= 1) {
        if (tid < off) red[tid] += red[tid + off];
        __syncthreads();
    }
    // red[0] holds this CTA's col-min sum; stays in smem across the barrier.

    // ---- Grid barrier: all 296 CTAs are co-resident (2/SM x 148) ----
    if (tid == 0) {
        __threadfence();                       // order atomicMax before ticket
        atomicAdd(&g_c1, 1);
        while (*(volatile int*)&g_c1 < NCTA) __nanosleep(64);
    }
    __syncthreads();
    __threadfence();                           // acquire: keys now stable in L2

    // ---- Phase 2: distributed fold (balanced slices), reset keys ----
    float f = 0.0f;
    {
        const int bx = blockIdx.x;             // recompute slices (no live regs)
        const int ks = (bx * NKEYS) / NCTA;
        const int ke = ((bx + 1) * NKEYS) / NCTA;
        for (int i = ks + tid; i < ke; i += THREADS) {
            f += dec_min(__ldcg(&g_rmkey[i]));
            g_rmkey[i] = 0u;                   // zero == +inf identity
        }
        const int zs = (bx * (BB * ZZ)) / NCTA;
        const int ze = ((bx + 1) * (BB * ZZ)) / NCTA;
        for (int i = zs + tid; i < ze; i += THREADS) {
            const float mm = mu[i];
            const float lv = logvar[i];
            f += -0.5f * (1.0f + lv - mm * mm - expf(lv));
        }
    }
    if (tid == 0) f += red[0];                 // fold own col-min sum (from smem)
    __syncthreads();                           // red[0] consumed before overwrite

    red[tid] = f;
    __syncthreads();
    for (int off = THREADS / 2; off > 0; off >>= 1) {
        if (tid < off) red[tid] += red[tid + off];
        __syncthreads();
    }

    if (tid == 0) {
        slast = 0;
        g_part2[blockIdx.x] = red[0];
        __threadfence();
        if (atomicAdd(&g_c2, 1) == NCTA - 1) slast = 1;
    }
    __syncthreads();

    // ---- Last CTA: final fold + write + ticket reset ----
    if (slast) {
        __threadfence();
        float t = 0.0f;
        for (int i = tid; i < NCTA; i += THREADS) t += __ldcg((float*)&g_part2[i]);
        red[tid] = t;
        __syncthreads();
        for (int off = THREADS / 2; off > 0; off >>= 1) {
            if (tid < off) red[tid] += red[tid + off];
            __syncthreads();
        }
        if (tid == 0) {
            out[0] = red[0];
            g_c1 = 0;          // reset tickets for next graph replay
            g_c2 = 0;
        }
    }
}

extern "C" void kernel_launch(void* const* d_in, const int* in_sizes, int n_in,
                              void* d_out, int out_size)
{
    const float* preds  = (const float*)d_in[0];   // [16, 3, 4096]
    const float* gts    = (const float*)d_in[1];   // [16, 3, 4096]
    const float* mu     = (const float*)d_in[2];   // [16, 128]
    const float* logvar = (const float*)d_in[3];   // [16, 128]
    float* out = (float*)d_out;

    chamfer_fused<<<NCTA, THREADS>>>(preds, gts, mu, logvar, out);
}

// round 17
// speedup vs baseline: 1.0941x; 1.0941x over previous
#include <cuda_runtime.h>
#include <math.h>

// Problem constants (fixed by the reference: B=16, N=4096, Z=128)
#define BB 16
#define NN 4096
#define ZZ 128

#define THREADS 512
#define Q 8                     // preds per thread: 512*8 = 4096 = ALL preds of the batch
#define NCTA 296                // 2 CTAs/SM on 148 SMs: all co-resident -> grid barrier safe
#define GTSMAX 232              // max gt-chunk (<=228 actual, padded)
#define NWARPS (THREADS / 32)   // 16
#define NKEYS (BB * NN)         // 65536

// Encoded row-min keys: zero-init == identity for atomicMax == +inf in min-space.
__device__ unsigned g_rmkey[NKEYS];     // 256KB, L2-resident
__device__ float    g_part2[NCTA];
__device__ int      g_c1 = 0;
__device__ int      g_c2 = 0;

// Full monotone-DECREASING float->uint map (min(v) <=> max(key)), identity 0.
__device__ __forceinline__ unsigned enc_min(float v) {
    unsigned b = __float_as_uint(v);
    return (b & 0x80000000u) ? b : (~b & 0x7FFFFFFFu);
}
__device__ __forceinline__ float dec_min(unsigned m) {
    return __uint_as_float((m & 0x80000000u) ? m : (~m & 0x7FFFFFFFu));
}

// CHEAP encoding for v >= 0 (true squared distances): key = ~bits, single LOP.
__device__ __forceinline__ unsigned enc_nn(float v) {
    return ~__float_as_uint(v);
}
__device__ __forceinline__ float dec_nn(unsigned m) {
    return __uint_as_float(~m);
}

// Warp-wide max reduction in ONE instruction.
__device__ __forceinline__ unsigned warp_redux_max(unsigned v) {
    unsigned r;
    asm("redux.sync.max.u32 %0, %1, 0xffffffff;" : "=r"(r) : "r"(v));
    return r;
}

// FFMA with immediate 1.0 multiplier: rt_SMSP=1
__device__ __forceinline__ float fma_i1(float a, float c) {
    float d;
    asm("fma.rn.f32 %0, %1, 0f3F800000, %2;" : "=f"(d) : "f"(a), "f"(c));
    return d;
}

// Persistent fused kernel (converged structure from R11/R14/R15 — best known).
// Phase 1: CTA = (batch, balanced gt-chunk), ALL 4096 preds in registers.
//   t' = (||g||^2 + ||p||^2) - 2 g.p = P[j,q]  (imm-FFMA seed + 3 FFMA)
//   row-min: mn[q] = min(mn[q], t')  -> global atomicMax key merge (exact)
//   col-min: ca    = min(ca,   t')  -> redux.sync key, stored one iter late
// Grid barrier (all 296 CTAs co-resident), distributed fold + KL, ticket-last
// CTA writes out[0]. One launch total.
__global__ __launch_bounds__(THREADS, 2)
void chamfer_fused(const float* __restrict__ preds,
                   const float* __restrict__ gts,
                   const float* __restrict__ mu,
                   const float* __restrict__ logvar,
                   float* __restrict__ out)
{
    __shared__ float4   sg[GTSMAX];             // (-2gx, -2gy, -2gz, ||g||^2)
    __shared__ unsigned scol[NWARPS * GTSMAX];  // per-warp col-min KEYS (~bits)
    __shared__ float    red[THREADS];
    __shared__ int      slast;

    // Balanced (batch, chunk) assignment: batches 0-7 -> 19 CTAs, 8-15 -> 18.
    const int cta = blockIdx.x;
    int batch, idx, C;
    if (cta < 152) { batch = cta / 19;            idx = cta % 19;        C = 19; }
    else           { batch = 8 + (cta - 152) / 18; idx = (cta - 152) % 18; C = 18; }
    const int gA  = 2 * ((idx * (NN / 2)) / C);              // even start
    const int cnt = 2 * (((idx + 1) * (NN / 2)) / C) - gA;   // even, <= 228

    const float* __restrict__ pb = preds + batch * 3 * NN;

    const int tid   = threadIdx.x;
    const int wid   = tid >> 5;
    const bool lane0 = (tid & 31) == 0;

    // Stage this CTA's gt chunk (coalesced per-channel loads, pre-scale by -2)
    {
        const float* __restrict__ gb = gts + batch * 3 * NN;
        for (int i = tid; i < cnt; i += THREADS) {
            const int n = gA + i;
            const float x0 = gb[n];
            const float x1 = gb[NN + n];
            const float x2 = gb[2 * NN + n];
            sg[i] = make_float4(-2.0f * x0, -2.0f * x1, -2.0f * x2,
                                x0 * x0 + x1 * x1 + x2 * x2);
        }
    }

    // This thread's 8 preds in registers
    float px[Q], py[Q], pz[Q], rp[Q], mn[Q];
#pragma unroll
    for (int q = 0; q < Q; q++) {
        const int m = tid + q * THREADS;
        px[q] = pb[m];
        py[q] = pb[NN + m];
        pz[q] = pb[2 * NN + m];
        rp[q] = px[q] * px[q] + py[q] * py[q] + pz[q] * pz[q];
        mn[q] = 3.4e38f;
    }
    __syncthreads();

    // Main sweep, 2 gts per iteration. The rp term is folded into the FFMA
    // seed, so t' = P[j,q] feeds BOTH mins directly (no post-dot imm-FFMA on
    // the critical path). Col keys stored one iteration late (pipelined).
    {
        unsigned* __restrict__ sc = scol + wid * GTSMAX;
        unsigned kp0 = 0u, kp1 = 0u;
        for (int j = 0; j < cnt; j += 2) {
            if (lane0 && j > 0) {          // store previous pair's keys
                sc[j - 2] = kp0;
                sc[j - 1] = kp1;
            }
            const float4 g0 = sg[j];
            const float4 g1 = sg[j + 1];
            float ca0 = 3.4e38f, ca1 = 3.4e38f;
#pragma unroll
            for (int q = 0; q < Q; q += 2) {
                const float s0a = fma_i1(g0.w, rp[q]);     // seeds: off critical path
                const float s0b = fma_i1(g0.w, rp[q+1]);
                const float s1a = fma_i1(g1.w, rp[q]);
                const float s1b = fma_i1(g1.w, rp[q+1]);
                float t00 = fmaf(g0.x, px[q],   fmaf(g0.y, py[q],   fmaf(g0.z, pz[q],   s0a)));
                float t01 = fmaf(g0.x, px[q+1], fmaf(g0.y, py[q+1], fmaf(g0.z, pz[q+1], s0b)));
                float t10 = fmaf(g1.x, px[q],   fmaf(g1.y, py[q],   fmaf(g1.z, pz[q],   s1a)));
                float t11 = fmaf(g1.x, px[q+1], fmaf(g1.y, py[q+1], fmaf(g1.z, pz[q+1], s1b)));
                mn[q]   = fminf(mn[q],   fminf(t00, t10));
                mn[q+1] = fminf(mn[q+1], fminf(t01, t11));
                ca0 = fminf(ca0, fminf(t00, t01));
                ca1 = fminf(ca1, fminf(t10, t11));
            }
            // ca0/ca1 are true squared distances (>= 0): single-NOT encoding.
            kp0 = warp_redux_max(enc_nn(ca0));
            kp1 = warp_redux_max(enc_nn(ca1));
        }
        if (lane0) {                       // drain the pipeline
            sc[cnt - 2] = kp0;
            sc[cnt - 1] = kp1;
        }
    }

    // Merge partial row-mins across gt-chunks: encoded atomicMax (full safe
    // encoding; exact, order-independent). mn already includes rp (it is P).
#pragma unroll
    for (int q = 0; q < Q; q++) {
        const int p = tid + q * THREADS;
        atomicMax(&g_rmkey[batch * NN + p], enc_min(mn[q]));
    }

    __syncthreads();

    // Cross-warp col-min reduce (integer max on ~bits keys) + sum over gts
    float s = 0.0f;
    for (int i = tid; i < cnt; i += THREADS) {
        unsigned c = scol[i];
#pragma unroll
        for (int w = 1; w < NWARPS; w++)
            c = max(c, scol[w * GTSMAX + i]);
        s += dec_nn(c);
    }
    red[tid] = s;
    __syncthreads();
    for (int off = THREADS / 2; off > 0; off >>= 1) {
        if (tid < off) red[tid] += red[tid + off];
        __syncthreads();
    }
    // red[0] holds this CTA's col-min sum; stays in smem across the barrier.

    // ---- Grid barrier: all 296 CTAs are co-resident (2/SM x 148) ----
    if (tid == 0) {
        __threadfence();                       // order atomicMax before ticket
        atomicAdd(&g_c1, 1);
        while (*(volatile int*)&g_c1 < NCTA) __nanosleep(64);
    }
    __syncthreads();
    __threadfence();                           // acquire: keys now stable in L2

    // ---- Phase 2: distributed fold (balanced slices), reset keys ----
    float f = 0.0f;
    {
        const int bx = blockIdx.x;             // recompute slices (no live regs)
        const int ks = (bx * NKEYS) / NCTA;
        const int ke = ((bx + 1) * NKEYS) / NCTA;
        for (int i = ks + tid; i < ke; i += THREADS) {
            f += dec_min(__ldcg(&g_rmkey[i]));
            g_rmkey[i] = 0u;                   // zero == +inf identity
        }
        const int zs = (bx * (BB * ZZ)) / NCTA;
        const int ze = ((bx + 1) * (BB * ZZ)) / NCTA;
        for (int i = zs + tid; i < ze; i += THREADS) {
            const float mm = mu[i];
            const float lv = logvar[i];
            f += -0.5f * (1.0f + lv - mm * mm - expf(lv));
        }
    }
    if (tid == 0) f += red[0];                 // fold own col-min sum (from smem)
    __syncthreads();                           // red[0] consumed before overwrite

    red[tid] = f;
    __syncthreads();
    for (int off = THREADS / 2; off > 0; off >>= 1) {
        if (tid < off) red[tid] += red[tid + off];
        __syncthreads();
    }

    if (tid == 0) {
        slast = 0;
        g_part2[blockIdx.x] = red[0];
        __threadfence();
        if (atomicAdd(&g_c2, 1) == NCTA - 1) slast = 1;
    }
    __syncthreads();

    // ---- Last CTA: final fold + write + ticket reset ----
    if (slast) {
        __threadfence();
        float t = 0.0f;
        for (int i = tid; i < NCTA; i += THREADS) t += __ldcg((float*)&g_part2[i]);
        red[tid] = t;
        __syncthreads();
        for (int off = THREADS / 2; off > 0; off >>= 1) {
            if (tid < off) red[tid] += red[tid + off];
            __syncthreads();
        }
        if (tid == 0) {
            out[0] = red[0];
            g_c1 = 0;          // reset tickets for next graph replay
            g_c2 = 0;
        }
    }
}

extern "C" void kernel_launch(void* const* d_in, const int* in_sizes, int n_in,
                              void* d_out, int out_size)
{
    const float* preds  = (const float*)d_in[0];   // [16, 3, 4096]
    const float* gts    = (const float*)d_in[1];   // [16, 3, 4096]
    const float* mu     = (const float*)d_in[2];   // [16, 128]
    const float* logvar = (const float*)d_in[3];   // [16, 128]
    float* out = (float*)d_out;

    chamfer_fused<<<NCTA, THREADS>>>(preds, gts, mu, logvar, out);
}